// round 12
// baseline (speedup 1.0000x reference)
#include <cuda_runtime.h>
#include <cstdint>

#define Nn   2048
#define Bb   8
#define KSEL 20
#define TPB  256
#define VPT  8          // Nn / TPB
#define NW   8          // TPB / 32

__device__ float g_scores[(size_t)Nn * Nn];   // 5*tanh(logits/5), computed once

__global__ void __launch_bounds__(TPB) eidx_kernel(float* __restrict__ out) {
    unsigned idx = blockIdx.x * TPB + threadIdx.x;
    const unsigned NN = (unsigned)Nn * (unsigned)Nn;
    if (idx < 2u * NN) {
        unsigned v = (idx < NN) ? (idx & (Nn - 1)) : ((idx - NN) >> 11);
        out[idx] = (float)v;
    }
}

__global__ void __launch_bounds__(TPB) scores_kernel(const float* __restrict__ logits) {
    unsigned idx = blockIdx.x * TPB + threadIdx.x;
    // bit-identical expression to the reference path used in earlier rounds
    g_scores[idx] = 5.0f * tanhf(__fdiv_rn(logits[idx], 5.0f));
}

__global__ void __launch_bounds__(TPB) sample_kernel(
    const float* __restrict__ gumbel,
    float* __restrict__ outw)      // weights region, [B*N, N] row-major
{
    const int row  = blockIdx.x;           // b*N + i
    const int i    = row & (Nn - 1);
    const int t    = threadIdx.x;
    const int lane = t & 31;
    const int warp = t >> 5;
    const unsigned FULL = 0xffffffffu;

    __shared__ __align__(16) float              sred[2][NW];
    __shared__ __align__(8)  unsigned long long aslot[3];

    const float* srow = g_scores + (size_t)i   * Nn;
    const float* grow = gumbel   + (size_t)row * Nn;

    if (t == 0) aslot[0] = 0ull;           // visible before round 0 (many barriers between)

    // ---- prologue: u0 = 2*(scores + gumbel), row max M0 ----
    float u0[VPT];
    float mloc = -3.402823466e38f;
#pragma unroll
    for (int v = 0; v < VPT; v++) {
        int j = v * TPB + t;
        float g0 = srow[j] + grow[j];
        u0[v] = 2.0f * g0;                 // g0 / tau, tau = 0.5 (exact)
        mloc = fmaxf(mloc, u0[v]);
    }
#pragma unroll
    for (int o = 16; o; o >>= 1) mloc = fmaxf(mloc, __shfl_xor_sync(FULL, mloc, o));
    if (lane == 0) sred[1][warp] = mloc;
    __syncthreads();
    {
        float4 ma = *(const float4*)&sred[1][0];
        float4 mb = *(const float4*)&sred[1][4];
        mloc = fmaxf(fmaxf(fmaxf(ma.x, ma.y), fmaxf(ma.z, ma.w)),
                     fmaxf(fmaxf(mb.x, mb.y), fmaxf(mb.z, mb.w)));
    }
    const float M0 = mloc;
    __syncthreads();

    // ---- E0 = exp(u0 - M0); loop maintains p = prod(max(1-oh,eps))^2 ----
    // (arithmetic bit-identical to the passing R7/R8 kernels)
    float E0[VPT], p[VPT], kh[VPT];
#pragma unroll
    for (int v = 0; v < VPT; v++) {
        E0[v] = expf(u0[v] - M0);
        p[v]  = 1.0f;
        kh[v] = 0.0f;
    }

    for (int k = 0; k < KSEL; k++) {
        float e[VPT];
#pragma unroll
        for (int v = 0; v < VPT; v++) e[v] = E0[v] * p[v];
        float s01 = e[0] + e[1], s23 = e[2] + e[3];
        float s45 = e[4] + e[5], s67 = e[6] + e[7];
        float sloc = (s01 + s23) + (s45 + s67);
#pragma unroll
        for (int o = 16; o; o >>= 1) sloc += __shfl_xor_sync(FULL, sloc, o);
        if (lane == 0) sred[k & 1][warp] = sloc;
        __syncthreads();
        float4 a = *(const float4*)&sred[k & 1][0];
        float4 b = *(const float4*)&sred[k & 1][4];
        float tot = ((a.x + a.y) + (a.z + a.w)) + ((b.x + b.y) + (b.z + b.w));
        float rs  = __fdiv_rn(1.0f, tot);
#pragma unroll
        for (int v = 0; v < VPT; v++) {
            float oh = e[v] * rs;
            kh[v] += oh;
            float tt = fmaxf(1.0f - oh, 1e-20f);
            p[v] *= tt * tt;
        }
    }

    // ---- top-K: cached per-thread argmax + smem atomicMax fold ----
    // khot >= 0 so float order == unsigned order on raw bits.
    unsigned key[VPT];
#pragma unroll
    for (int v = 0; v < VPT; v++) key[v] = __float_as_uint(kh[v]);
    unsigned hard = 0;
    const unsigned rbase = 2047u - (unsigned)t;   // rank (2047 - j) for v=0

    // per-thread cached max: value bits + rank (tie -> higher rank = lower idx)
    unsigned cm = key[0];
    unsigned cr = rbase;
#pragma unroll
    for (int v = 1; v < VPT; v++) {
        unsigned rk = rbase - (unsigned)(v * TPB);
        if (key[v] > cm) { cm = key[v]; cr = rk; }
    }

    int slot = 0, nslot = 1;
    for (int r = 0; r < KSEL; r++) {
        unsigned kloc = __reduce_max_sync(FULL, cm);
        unsigned iloc = __reduce_max_sync(FULL, (cm == kloc) ? cr : 0u);
        if (lane == 0)
            atomicMax(&aslot[slot], ((unsigned long long)kloc << 32) | iloc);
        if (t == 0) aslot[nslot] = 0ull;   // prepare slot for round r+1 (3-slot rotation)
        __syncthreads();
        unsigned long long best = aslot[slot];
        slot = nslot; nslot = (nslot == 2) ? 0 : nslot + 1;
        unsigned j = 2047u - (unsigned)(best & 0xFFFFFFFFull);
        if ((int)(j & (TPB - 1)) == t) {
            int v = (int)(j >> 8);
            hard |= (1u << v);
#pragma unroll
            for (int w = 0; w < VPT; w++)
                if (w == v) key[w] = 0u;   // khot > 0 always, so 0 never matches
            // rescan this thread's 8 keys (rare: one thread per round)
            cm = key[0];
            cr = rbase;
#pragma unroll
            for (int w = 1; w < VPT; w++) {
                unsigned rk = rbase - (unsigned)(w * TPB);
                if (key[w] > cm) { cm = key[w]; cr = rk; }
            }
        }
    }

    // ---- write: forward value of khot_hard + khot - stop_grad(khot) ----
    float* orow = outw + (size_t)row * Nn;
#pragma unroll
    for (int v = 0; v < VPT; v++) {
        int j = v * TPB + t;
        float s = kh[v];
        float one = (1.0f + s) - s;        // replicate reference fp rounding
        orow[j] = ((hard >> v) & 1u) ? one : 0.0f;
    }
}

extern "C" void kernel_launch(void* const* d_in, const int* in_sizes, int n_in,
                              void* d_out, int out_size) {
    const float* logits = (const float*)d_in[0];
    const float* gumbel = (const float*)d_in[1];
    float* out = (float*)d_out;

    const size_t NN = (size_t)Nn * (size_t)Nn;
    float* wbase = out;

    if ((size_t)out_size >= 2 * NN + (size_t)Bb * NN) {
        // layout: [edge_index (2*N*N as float)] [edge_weight (B*N*N)]
        unsigned total = 2u * (unsigned)NN;
        eidx_kernel<<<(total + TPB - 1) / TPB, TPB>>>(out);
        wbase = out + 2 * NN;
    }
    scores_kernel<<<(unsigned)(NN / TPB), TPB>>>(logits);
    sample_kernel<<<Bb * Nn, TPB>>>(gumbel, wbase);
}

// round 13
// speedup vs baseline: 1.0046x; 1.0046x over previous
#include <cuda_runtime.h>
#include <cstdint>

#define Nn   2048
#define Bb   8
#define KSEL 20
#define TPB  256
#define VPT  8          // Nn / TPB
#define NW   8          // TPB / 32

__device__ float g_scores[(size_t)Nn * Nn];   // 5*tanh(logits/5), computed once

__global__ void __launch_bounds__(TPB) eidx_kernel(float* __restrict__ out) {
    unsigned idx = blockIdx.x * TPB + threadIdx.x;
    const unsigned NN = (unsigned)Nn * (unsigned)Nn;
    if (idx < 2u * NN) {
        unsigned v = (idx < NN) ? (idx & (Nn - 1)) : ((idx - NN) >> 11);
        out[idx] = (float)v;
    }
}

__global__ void __launch_bounds__(TPB) scores_kernel(const float* __restrict__ logits) {
    unsigned idx = blockIdx.x * TPB + threadIdx.x;
    // bit-identical expression to the reference path used in earlier rounds
    g_scores[idx] = 5.0f * tanhf(__fdiv_rn(logits[idx], 5.0f));
}

__global__ void __launch_bounds__(TPB) sample_kernel(
    const float* __restrict__ gumbel,
    float* __restrict__ outw)      // weights region, [B*N, N] row-major
{
    const int row  = blockIdx.x;           // b*N + i
    const int i    = row & (Nn - 1);
    const int t    = threadIdx.x;
    const int lane = t & 31;
    const int warp = t >> 5;
    const unsigned FULL = 0xffffffffu;

    __shared__ __align__(16) float              sred[2][NW];
    __shared__ __align__(8)  unsigned long long aslot[3];

    const float* srow = g_scores + (size_t)i   * Nn;
    const float* grow = gumbel   + (size_t)row * Nn;

    if (t == 0) aslot[0] = 0ull;           // visible before round 0 (many barriers between)

    // ---- prologue: u0 = 2*(scores + gumbel), row max M0 ----
    float u0[VPT];
    float mloc = -3.402823466e38f;
#pragma unroll
    for (int v = 0; v < VPT; v++) {
        int j = v * TPB + t;
        float g0 = srow[j] + grow[j];
        u0[v] = 2.0f * g0;                 // g0 / tau, tau = 0.5 (exact)
        mloc = fmaxf(mloc, u0[v]);
    }
#pragma unroll
    for (int o = 16; o; o >>= 1) mloc = fmaxf(mloc, __shfl_xor_sync(FULL, mloc, o));
    if (lane == 0) sred[1][warp] = mloc;
    __syncthreads();
    {
        float4 ma = *(const float4*)&sred[1][0];
        float4 mb = *(const float4*)&sred[1][4];
        mloc = fmaxf(fmaxf(fmaxf(ma.x, ma.y), fmaxf(ma.z, ma.w)),
                     fmaxf(fmaxf(mb.x, mb.y), fmaxf(mb.z, mb.w)));
    }
    const float M0 = mloc;
    __syncthreads();

    // ---- E0 = exp(u0 - M0); loop maintains p = prod(max(1-oh,eps))^2 ----
    // (arithmetic bit-identical to the passing R7/R8 kernels)
    float E0[VPT], p[VPT], kh[VPT];
#pragma unroll
    for (int v = 0; v < VPT; v++) {
        E0[v] = expf(u0[v] - M0);
        p[v]  = 1.0f;
        kh[v] = 0.0f;
    }

    for (int k = 0; k < KSEL; k++) {
        float e[VPT];
#pragma unroll
        for (int v = 0; v < VPT; v++) e[v] = E0[v] * p[v];
        float s01 = e[0] + e[1], s23 = e[2] + e[3];
        float s45 = e[4] + e[5], s67 = e[6] + e[7];
        float sloc = (s01 + s23) + (s45 + s67);
#pragma unroll
        for (int o = 16; o; o >>= 1) sloc += __shfl_xor_sync(FULL, sloc, o);
        if (lane == 0) sred[k & 1][warp] = sloc;
        __syncthreads();
        float4 a = *(const float4*)&sred[k & 1][0];
        float4 b = *(const float4*)&sred[k & 1][4];
        float tot = ((a.x + a.y) + (a.z + a.w)) + ((b.x + b.y) + (b.z + b.w));
        float rs  = __fdiv_rn(1.0f, tot);
#pragma unroll
        for (int v = 0; v < VPT; v++) {
            float oh = e[v] * rs;
            kh[v] += oh;
            float tt = fmaxf(1.0f - oh, 1e-20f);
            p[v] *= tt * tt;
        }
    }

    // ---- top-K: cached per-thread argmax + smem atomicMax fold ----
    // khot >= 0 so float order == unsigned order on raw bits.
    unsigned key[VPT];
#pragma unroll
    for (int v = 0; v < VPT; v++) key[v] = __float_as_uint(kh[v]);
    unsigned hard = 0;
    const unsigned rbase = 2047u - (unsigned)t;   // rank (2047 - j) for v=0

    // per-thread cached max: value bits + rank (tie -> higher rank = lower idx)
    unsigned cm = key[0];
    unsigned cr = rbase;
#pragma unroll
    for (int v = 1; v < VPT; v++) {
        unsigned rk = rbase - (unsigned)(v * TPB);
        if (key[v] > cm) { cm = key[v]; cr = rk; }
    }

    int slot = 0, nslot = 1;
    for (int r = 0; r < KSEL; r++) {
        unsigned kloc = __reduce_max_sync(FULL, cm);
        unsigned iloc = __reduce_max_sync(FULL, (cm == kloc) ? cr : 0u);
        if (lane == 0)
            atomicMax(&aslot[slot], ((unsigned long long)kloc << 32) | iloc);
        if (t == 0) aslot[nslot] = 0ull;   // prepare slot for round r+1 (3-slot rotation)
        __syncthreads();
        unsigned long long best = aslot[slot];
        slot = nslot; nslot = (nslot == 2) ? 0 : nslot + 1;
        unsigned j = 2047u - (unsigned)(best & 0xFFFFFFFFull);
        if ((int)(j & (TPB - 1)) == t) {
            int v = (int)(j >> 8);
            hard |= (1u << v);
#pragma unroll
            for (int w = 0; w < VPT; w++)
                if (w == v) key[w] = 0u;   // khot > 0 always, so 0 never matches
            // rescan this thread's 8 keys (rare: one thread per round)
            cm = key[0];
            cr = rbase;
#pragma unroll
            for (int w = 1; w < VPT; w++) {
                unsigned rk = rbase - (unsigned)(w * TPB);
                if (key[w] > cm) { cm = key[w]; cr = rk; }
            }
        }
    }

    // ---- write: forward value of khot_hard + khot - stop_grad(khot) ----
    float* orow = outw + (size_t)row * Nn;
#pragma unroll
    for (int v = 0; v < VPT; v++) {
        int j = v * TPB + t;
        float s = kh[v];
        float one = (1.0f + s) - s;        // replicate reference fp rounding
        orow[j] = ((hard >> v) & 1u) ? one : 0.0f;
    }
}

extern "C" void kernel_launch(void* const* d_in, const int* in_sizes, int n_in,
                              void* d_out, int out_size) {
    const float* logits = (const float*)d_in[0];
    const float* gumbel = (const float*)d_in[1];
    float* out = (float*)d_out;

    const size_t NN = (size_t)Nn * (size_t)Nn;
    float* wbase = out;

    if ((size_t)out_size >= 2 * NN + (size_t)Bb * NN) {
        // layout: [edge_index (2*N*N as float)] [edge_weight (B*N*N)]
        unsigned total = 2u * (unsigned)NN;
        eidx_kernel<<<(total + TPB - 1) / TPB, TPB>>>(out);
        wbase = out + 2 * NN;
    }
    scores_kernel<<<(unsigned)(NN / TPB), TPB>>>(logits);
    sample_kernel<<<Bb * Nn, TPB>>>(gumbel, wbase);
}

// round 14
// speedup vs baseline: 1.0059x; 1.0013x over previous
#include <cuda_runtime.h>
#include <cstdint>

#define Nn   2048
#define Bb   8
#define KSEL 20
#define TPB  256
#define VPT  8          // Nn / TPB
#define NW   8          // TPB / 32

__device__ float g_scores[(size_t)Nn * Nn];   // 5*tanh(logits/5), computed once

__global__ void __launch_bounds__(TPB) eidx_kernel(float* __restrict__ out) {
    unsigned idx = blockIdx.x * TPB + threadIdx.x;
    const unsigned NN = (unsigned)Nn * (unsigned)Nn;
    if (idx < 2u * NN) {
        unsigned v = (idx < NN) ? (idx & (Nn - 1)) : ((idx - NN) >> 11);
        out[idx] = (float)v;
    }
}

__global__ void __launch_bounds__(TPB) scores_kernel(const float* __restrict__ logits) {
    unsigned idx = blockIdx.x * TPB + threadIdx.x;
    // bit-identical expression to the reference path used in earlier rounds
    g_scores[idx] = 5.0f * tanhf(__fdiv_rn(logits[idx], 5.0f));
}

__global__ void __launch_bounds__(TPB) sample_kernel(
    const float* __restrict__ gumbel,
    float* __restrict__ outw)      // weights region, [B*N, N] row-major
{
    const int row  = blockIdx.x;           // b*N + i
    const int i    = row & (Nn - 1);
    const int t    = threadIdx.x;
    const int lane = t & 31;
    const int warp = t >> 5;
    const unsigned FULL = 0xffffffffu;

    __shared__ __align__(16) float              sred[2][NW];
    __shared__ __align__(8)  unsigned long long aslot[3];

    const float* srow = g_scores + (size_t)i   * Nn;
    const float* grow = gumbel   + (size_t)row * Nn;

    if (t == 0) aslot[0] = 0ull;           // visible before round 0 (many barriers between)

    // ---- prologue: u0 = 2*(scores + gumbel), row max M0 ----
    float u0[VPT];
    float mloc = -3.402823466e38f;
#pragma unroll
    for (int v = 0; v < VPT; v++) {
        int j = v * TPB + t;
        float g0 = srow[j] + grow[j];
        u0[v] = 2.0f * g0;                 // g0 / tau, tau = 0.5 (exact)
        mloc = fmaxf(mloc, u0[v]);
    }
#pragma unroll
    for (int o = 16; o; o >>= 1) mloc = fmaxf(mloc, __shfl_xor_sync(FULL, mloc, o));
    if (lane == 0) sred[1][warp] = mloc;
    __syncthreads();
    {
        float4 ma = *(const float4*)&sred[1][0];
        float4 mb = *(const float4*)&sred[1][4];
        mloc = fmaxf(fmaxf(fmaxf(ma.x, ma.y), fmaxf(ma.z, ma.w)),
                     fmaxf(fmaxf(mb.x, mb.y), fmaxf(mb.z, mb.w)));
    }
    const float M0 = mloc;
    __syncthreads();

    // ---- E0 = exp(u0 - M0); loop maintains p = prod(max(1-oh,eps))^2 ----
    // (arithmetic bit-identical to the passing R7/R8 kernels)
    float E0[VPT], p[VPT], kh[VPT];
#pragma unroll
    for (int v = 0; v < VPT; v++) {
        E0[v] = expf(u0[v] - M0);
        p[v]  = 1.0f;
        kh[v] = 0.0f;
    }

    for (int k = 0; k < KSEL; k++) {
        float e[VPT];
#pragma unroll
        for (int v = 0; v < VPT; v++) e[v] = E0[v] * p[v];
        float s01 = e[0] + e[1], s23 = e[2] + e[3];
        float s45 = e[4] + e[5], s67 = e[6] + e[7];
        float sloc = (s01 + s23) + (s45 + s67);
#pragma unroll
        for (int o = 16; o; o >>= 1) sloc += __shfl_xor_sync(FULL, sloc, o);
        if (lane == 0) sred[k & 1][warp] = sloc;
        __syncthreads();
        float4 a = *(const float4*)&sred[k & 1][0];
        float4 b = *(const float4*)&sred[k & 1][4];
        float tot = ((a.x + a.y) + (a.z + a.w)) + ((b.x + b.y) + (b.z + b.w));
        float rs  = __fdiv_rn(1.0f, tot);
#pragma unroll
        for (int v = 0; v < VPT; v++) {
            float oh = e[v] * rs;
            kh[v] += oh;
            float tt = fmaxf(1.0f - oh, 1e-20f);
            p[v] *= tt * tt;
        }
    }

    // ---- top-K: cached per-thread argmax + smem atomicMax fold ----
    // khot >= 0 so float order == unsigned order on raw bits.
    unsigned key[VPT];
#pragma unroll
    for (int v = 0; v < VPT; v++) key[v] = __float_as_uint(kh[v]);
    unsigned hard = 0;
    const unsigned rbase = 2047u - (unsigned)t;   // rank (2047 - j) for v=0

    // per-thread cached max: value bits + rank (tie -> higher rank = lower idx)
    unsigned cm = key[0];
    unsigned cr = rbase;
#pragma unroll
    for (int v = 1; v < VPT; v++) {
        unsigned rk = rbase - (unsigned)(v * TPB);
        if (key[v] > cm) { cm = key[v]; cr = rk; }
    }

    int slot = 0, nslot = 1;
    for (int r = 0; r < KSEL; r++) {
        unsigned kloc = __reduce_max_sync(FULL, cm);
        unsigned iloc = __reduce_max_sync(FULL, (cm == kloc) ? cr : 0u);
        if (lane == 0)
            atomicMax(&aslot[slot], ((unsigned long long)kloc << 32) | iloc);
        if (t == 0) aslot[nslot] = 0ull;   // prepare slot for round r+1 (3-slot rotation)
        __syncthreads();
        unsigned long long best = aslot[slot];
        slot = nslot; nslot = (nslot == 2) ? 0 : nslot + 1;
        unsigned j = 2047u - (unsigned)(best & 0xFFFFFFFFull);
        if ((int)(j & (TPB - 1)) == t) {
            int v = (int)(j >> 8);
            hard |= (1u << v);
#pragma unroll
            for (int w = 0; w < VPT; w++)
                if (w == v) key[w] = 0u;   // khot > 0 always, so 0 never matches
            // rescan this thread's 8 keys (rare: one thread per round)
            cm = key[0];
            cr = rbase;
#pragma unroll
            for (int w = 1; w < VPT; w++) {
                unsigned rk = rbase - (unsigned)(w * TPB);
                if (key[w] > cm) { cm = key[w]; cr = rk; }
            }
        }
    }

    // ---- write: forward value of khot_hard + khot - stop_grad(khot) ----
    float* orow = outw + (size_t)row * Nn;
#pragma unroll
    for (int v = 0; v < VPT; v++) {
        int j = v * TPB + t;
        float s = kh[v];
        float one = (1.0f + s) - s;        // replicate reference fp rounding
        orow[j] = ((hard >> v) & 1u) ? one : 0.0f;
    }
}

extern "C" void kernel_launch(void* const* d_in, const int* in_sizes, int n_in,
                              void* d_out, int out_size) {
    const float* logits = (const float*)d_in[0];
    const float* gumbel = (const float*)d_in[1];
    float* out = (float*)d_out;

    const size_t NN = (size_t)Nn * (size_t)Nn;
    float* wbase = out;

    if ((size_t)out_size >= 2 * NN + (size_t)Bb * NN) {
        // layout: [edge_index (2*N*N as float)] [edge_weight (B*N*N)]
        unsigned total = 2u * (unsigned)NN;
        eidx_kernel<<<(total + TPB - 1) / TPB, TPB>>>(out);
        wbase = out + 2 * NN;
    }
    scores_kernel<<<(unsigned)(NN / TPB), TPB>>>(logits);
    sample_kernel<<<Bb * Nn, TPB>>>(gumbel, wbase);
}